// round 12
// baseline (speedup 1.0000x reference)
#include <cuda_runtime.h>
#include <cuda_fp16.h>
#include <cstddef>
#include <cstdint>

#define NN 4096
#define FF 256
#define KK 8
#define FP 64
#define KF 512   // KK*FP

typedef unsigned int u32;

// ---------------- scratch (static device globals; no allocation) ----------------
__device__ float  g_xe[NN * KF];          // 8 MB xe[n][k*64+f] (f32, biased)
__device__ __half g_xeT[KF * NN];         // 4 MB xeT[k*64+f][n] (fp16)
__device__ float  g_hl[KK * NN];
__device__ float  g_hr[KK * NN];
__device__ u32    g_mbits[NN * (NN / 32)]; // 2 MB bit-packed mask
__device__ int    g_code;                  // 0=u8/bool, 1=int32, 2=float32

// ---------------- mask accessor (dtype decided at runtime) ----------------
__device__ __forceinline__ unsigned mask_at(const void* m, int code, size_t idx) {
    if (code == 0)      return (unsigned)((const unsigned char*)m)[idx];
    else if (code == 1) return ((const int*)m)[idx] != 0;
    else                return __float_as_uint(((const float*)m)[idx]) != 0u;
}

// ---------------- K0: mask dtype detection (single block) ----------------
__global__ void k_detect1(const void* mask) {
    __shared__ u32 sh0, sh1;
    if (threadIdx.x == 0) { sh0 = 0u; sh1 = 0u; }
    __syncthreads();
    const u32* wp = (const u32*)mask;
    u32 o0 = 0u, o1 = 0u;
    for (int i = threadIdx.x; i < 8192; i += 256) {   // 32 KB scan (mask >= 16 MB)
        u32 v = wp[i];
        o0 |= (v & 0xFFu);
        o1 |= ((v >> 8) & 0xFFu);
    }
    atomicOr(&sh0, o0);
    atomicOr(&sh1, o1);
    __syncthreads();
    // bool: random bytes everywhere -> sh1!=0. int32 0/1: byte1==0, byte0!=0.
    // float 0/1.0f: bytes 0,1 == 0.
    if (threadIdx.x == 0) g_code = sh1 ? 0 : (sh0 ? 1 : 2);
}

// ---------------- K0b: bit-pack mask: 16 MB -> 2 MB ----------------
__global__ void __launch_bounds__(256) k_bitpack(const void* __restrict__ mask) {
    int idx = blockIdx.x * blockDim.x + threadIdx.x;   // 0 .. NN*128-1
    int code = g_code;
    u32 bits = 0u;
    if (code == 0) {
        const u32* wp = (const u32*)mask + (size_t)idx * 8;
#pragma unroll
        for (int i = 0; i < 8; i++) {
            u32 v = wp[i];
            bits |= ((v & 1u) << (4 * i)) | (((v >> 8) & 1u) << (4 * i + 1)) |
                    (((v >> 16) & 1u) << (4 * i + 2)) | (((v >> 24) & 1u) << (4 * i + 3));
        }
    } else {
        size_t base = (size_t)idx * 32;
        for (int j = 0; j < 32; j++)
            bits |= mask_at(mask, code, base + j) << j;
    }
    g_mbits[idx] = bits;
}

// ---------------- K1: xe = x @ W^T + b, fused hl/hr ----------------
// blockIdx.x = head k (64 cols = exactly one head) -> exact hl/hr, no atomics.
__global__ void __launch_bounds__(256) gemm_xe(const float* __restrict__ x,
                                               const float* __restrict__ W,
                                               const float* __restrict__ b,
                                               const float* __restrict__ aL,
                                               const float* __restrict__ aR) {
    __shared__ float sA[16][68];
    __shared__ float sB[16][68];
    int tid = threadIdx.x;
    int tx = tid & 15, ty = tid >> 4;
    int row0 = blockIdx.y * 64;
    int head = blockIdx.x;
    int col0 = head * 64;
    float acc[4][4];
#pragma unroll
    for (int i = 0; i < 4; i++)
#pragma unroll
        for (int j = 0; j < 4; j++) acc[i][j] = 0.f;

    for (int t = 0; t < FF / 16; t++) {
#pragma unroll
        for (int l = 0; l < 4; l++) {
            int idx = tid + l * 256;
            int mm = idx >> 4, kk = idx & 15;
            sA[kk][mm] = x[(size_t)(row0 + mm) * FF + t * 16 + kk];
            sB[kk][mm] = W[(size_t)(col0 + mm) * FF + t * 16 + kk];
        }
        __syncthreads();
#pragma unroll
        for (int kk = 0; kk < 16; kk++) {
            float a[4], bv[4];
#pragma unroll
            for (int i = 0; i < 4; i++) a[i] = sA[kk][ty * 4 + i];
#pragma unroll
            for (int j = 0; j < 4; j++) bv[j] = sB[kk][tx * 4 + j];
#pragma unroll
            for (int i = 0; i < 4; i++)
#pragma unroll
                for (int j = 0; j < 4; j++) acc[i][j] += a[i] * bv[j];
        }
        __syncthreads();
    }

    // bias + store + hl/hr partials (over this thread's 4 cols)
    float hlv[4] = {0.f, 0.f, 0.f, 0.f}, hrv[4] = {0.f, 0.f, 0.f, 0.f};
#pragma unroll
    for (int j = 0; j < 4; j++) {
        int c = col0 + tx * 4 + j;
        float aLj = aL[head * FP + tx * 4 + j];
        float aRj = aR[head * FP + tx * 4 + j];
        float bj = b[c];
#pragma unroll
        for (int i = 0; i < 4; i++) {
            float v = acc[i][j] + bj;
            acc[i][j] = v;
            hlv[i] += v * aLj;
            hrv[i] += v * aRj;
            g_xe[(size_t)(row0 + ty * 4 + i) * KF + c] = v;
        }
    }
    // reduce across the 16 tx lanes (xor 8,4,2,1 stays in 16-lane halves)
#pragma unroll
    for (int i = 0; i < 4; i++) {
#pragma unroll
        for (int off = 8; off; off >>= 1) {
            hlv[i] += __shfl_xor_sync(0xffffffffu, hlv[i], off);
            hrv[i] += __shfl_xor_sync(0xffffffffu, hrv[i], off);
        }
    }
    if (tx == 0) {
#pragma unroll
        for (int i = 0; i < 4; i++) {
            int n = row0 + ty * 4 + i;
            g_hl[head * NN + n] = hlv[i];
            g_hr[head * NN + n] = hrv[i];
        }
    }
}

// ---------------- K2: transpose xe -> fp16 xeT[k*64+f][n] ----------------
__global__ void __launch_bounds__(256) k_xt() {
    __shared__ float tile[32][33];
    int tx = threadIdx.x & 31, ty = threadIdx.x >> 5;   // ty 0..7
    int c0 = blockIdx.x * 32;   // col in KF
    int n0 = blockIdx.y * 32;   // row in NN
#pragma unroll
    for (int i = 0; i < 4; i++)
        tile[ty + 8 * i][tx] = g_xe[(size_t)(n0 + ty + 8 * i) * KF + c0 + tx];
    __syncthreads();
#pragma unroll
    for (int i = 0; i < 4; i++)
        g_xeT[(size_t)(c0 + ty + 8 * i) * NN + n0 + tx] =
            __float2half_rn(tile[tx][ty + 8 * i]);
}

// ---------------- K3: fused attention (fp16 m16n8k16 mma, double-buffered) ----
// Block 128 thr (4 warps), CTA = (head kh, 64 n-rows); warp w owns rows w*16..+15.
// No max-subtraction (e bounded: exp(e) <= ~1e3 << fp16 max); softmax shift-inv.
#define TMA 64
#define BKA 32
#define NTA (NN / BKA)

__device__ __forceinline__ float elu2(float h) {
    if (h <= 0.f) {
        h = __expf(h) - 1.0f;      // elu #1
        h = __expf(h) - 1.0f;      // elu #2 (input <= 0 here)
    }
    return h;
}

__global__ void __launch_bounds__(128) k_attn(float* __restrict__ out) {
    int kh = blockIdx.y;
    int n0 = blockIdx.x * TMA;
    int tid = threadIdx.x;
    int lane = tid & 31, w = tid >> 5;
    int gid = lane >> 2, tig = lane & 3;
    int row0 = w * 16;

    // pitch 40 halves (80 B): fragment u32 LDS conflict-free; 16B-aligned rows
    __shared__ __align__(16) __half s_p[2][TMA][40];
    __shared__ __align__(16) __half s_xt[2][TMA][40];
    __shared__ float s_hl[TMA], s_sum[TMA];

    if (tid < TMA) s_hl[tid] = g_hl[kh * NN + n0 + tid];
    __syncthreads();

    float acc[8][4];
#pragma unroll
    for (int t = 0; t < 8; t++)
#pragma unroll
        for (int q = 0; q < 4; q++) acc[t][q] = 0.f;
    float sumreg[16];
#pragma unroll
    for (int r = 0; r < 16; r++) sumreg[r] = 0.f;

    // xt staging: thread copies 16 consecutive halves (two uint4) of one f-row
    // 128 thr x 16 halves = 2048 = full 64x32 tile.  FIX vs R11 (was 8/thread).
    int xr = tid >> 1;            // 0..63 (f row)
    int xs = (tid & 1) * 16;      // half offset 0 / 16

#define STAGE(m0, bsel)                                                          \
    do {                                                                         \
        const __half* xsrc = (const __half*)g_xeT +                              \
                             (size_t)(kh * FP + xr) * NN + (m0) + xs;            \
        uint4 xv0 = *(const uint4*)(xsrc);                                       \
        uint4 xv1 = *(const uint4*)(xsrc + 8);                                   \
        *(uint4*)(&s_xt[bsel][xr][xs])     = xv0;                                \
        *(uint4*)(&s_xt[bsel][xr][xs + 8]) = xv1;                                \
        /* P tile: warp w rows row0..+15, lane = m */                            \
        float hrv = g_hr[kh * NN + (m0) + lane];                                 \
        int mw = (m0) >> 5;                                                      \
        _Pragma("unroll")                                                        \
        for (int r = 0; r < 16; r++) {                                           \
            int row = row0 + r;                                                  \
            u32 bt = g_mbits[(size_t)(n0 + row) * (NN / 32) + mw];               \
            float e = s_hl[row] + hrv;                                           \
            e = fmaxf(e, 0.2f * e);                    /* leaky */               \
            float p = ((bt >> lane) & 1u) ? __expf(e) : 0.0f;                    \
            __half ph = __float2half_rn(p);                                      \
            s_p[bsel][row][lane] = ph;                                           \
            sumreg[r] += __half2float(ph);  /* sum matches mma operand */        \
        }                                                                        \
    } while (0)

    STAGE(0, 0);

    for (int mb = 0; mb < NTA; mb++) {
        int cur = mb & 1;
        __syncthreads();   // staging of cur visible; prior mma on cur^1 done

        if (mb + 1 < NTA) STAGE((mb + 1) * BKA, cur ^ 1);

        // --- mma: o[16][64] += P[16][32] @ xeT[64][32]^T per warp (fp16 k16) ---
#pragma unroll
        for (int ks = 0; ks < 2; ks++) {
            int kb = ks * 16;
            u32 a0 = *(const u32*)(&s_p[cur][row0 + gid][kb + 2 * tig]);
            u32 a1 = *(const u32*)(&s_p[cur][row0 + gid + 8][kb + 2 * tig]);
            u32 a2 = *(const u32*)(&s_p[cur][row0 + gid][kb + 2 * tig + 8]);
            u32 a3 = *(const u32*)(&s_p[cur][row0 + gid + 8][kb + 2 * tig + 8]);
#pragma unroll
            for (int t = 0; t < 8; t++) {
                u32 b0 = *(const u32*)(&s_xt[cur][t * 8 + gid][kb + 2 * tig]);
                u32 b1 = *(const u32*)(&s_xt[cur][t * 8 + gid][kb + 2 * tig + 8]);
                asm("mma.sync.aligned.m16n8k16.row.col.f32.f16.f16.f32 "
                    "{%0,%1,%2,%3}, {%4,%5,%6,%7}, {%8,%9}, {%0,%1,%2,%3};"
                    : "+f"(acc[t][0]), "+f"(acc[t][1]),
                      "+f"(acc[t][2]), "+f"(acc[t][3])
                    : "r"(a0), "r"(a1), "r"(a2), "r"(a3), "r"(b0), "r"(b1));
            }
        }
    }
#undef STAGE

    // --- row sums (once) ---
#pragma unroll
    for (int r = 0; r < 16; r++) {
        float s = sumreg[r];
#pragma unroll
        for (int off = 16; off; off >>= 1)
            s += __shfl_xor_sync(0xffffffffu, s, off);
        if (lane == 0) s_sum[row0 + r] = s;
    }
    __syncthreads();

    // --- epilogue: normalize, double-ELU, store ---
#pragma unroll
    for (int half = 0; half < 2; half++) {
        int row = row0 + gid + half * 8;
        float inv = 1.0f / s_sum[row];
#pragma unroll
        for (int t = 0; t < 8; t++) {
            float va = elu2(acc[t][2 * half + 0] * inv);
            float vb = elu2(acc[t][2 * half + 1] * inv);
            size_t base = (size_t)(n0 + row) * KF + kh * FP + t * 8 + 2 * tig;
            *(float2*)(&out[base]) = make_float2(va, vb);
        }
    }
}

// ---------------- K4: write mask back as second tuple element ----------------
__global__ void k_write_mask(const void* __restrict__ mask, float* __restrict__ out,
                             long extra) {
    int code = g_code;
    long stride = (long)gridDim.x * blockDim.x;
    for (long i = (long)blockIdx.x * blockDim.x + threadIdx.x; i < extra; i += stride) {
        float v = 0.f;
        if (i < (long)NN * NN) v = mask_at(mask, code, (size_t)i) ? 1.f : 0.f;
        out[(long)NN * KF + i] = v;
    }
}

// ---------------- launch ----------------
extern "C" void kernel_launch(void* const* d_in, const int* in_sizes, int n_in,
                              void* d_out, int out_size) {
    const float* x  = (const float*)d_in[0];
    const float* W  = (const float*)d_in[1];
    const float* b  = (const float*)d_in[2];
    const float* aL = (const float*)d_in[3];
    const float* aR = (const float*)d_in[4];
    const void*  mk = d_in[5];
    float* out = (float*)d_out;

    k_detect1<<<1, 256>>>(mk);
    k_bitpack<<<NN * (NN / 32) / 256, 256>>>(mk);

    dim3 g1(KK, NN / 64);                 // (8, 64): blockIdx.x = head
    gemm_xe<<<g1, 256>>>(x, W, b, aL, aR);

    dim3 g2(KF / 32, NN / 32);            // (16, 128)
    k_xt<<<g2, 256>>>();

    dim3 g3(NN / TMA, KK);                // (64, 8) = 512 CTAs
    k_attn<<<g3, 128>>>(out);

    long extra = (long)out_size - (long)NN * KF;
    if (extra > 0)
        k_write_mask<<<1024, 256>>>(mk, out, extra);
}

// round 13
// speedup vs baseline: 1.6054x; 1.6054x over previous
#include <cuda_runtime.h>
#include <cuda_fp16.h>
#include <cstddef>
#include <cstdint>

#define NN 4096
#define FF 256
#define KK 8
#define FP 64
#define KF 512   // KK*FP

#define BKA 32
#define NTA (NN / BKA)        // 128 m-tiles total
#define TMA 64                // n-rows per CTA
#define SPLIT 2
#define MSPL (NN / SPLIT)     // 2048 m per split
#define TPS (MSPL / BKA)      // 64 tiles per CTA

typedef unsigned int u32;

// ---------------- scratch (static device globals; no allocation) ----------------
__device__ float  g_xe[NN * KF];            // 8 MB xe[n][k*64+f]
__device__ __half g_xeT[KK * NTA * FP * BKA]; // 4 MB tiled: [k][mtile][f][32]
__device__ float  g_hl[KK * NN];
__device__ float  g_hr[KK * NN];
__device__ u32    g_mbits[NN * (NN / 32)];  // 2 MB bit-packed mask
__device__ float  g_po[SPLIT * NN * KF];    // 16 MB partial O
__device__ float  g_ps[SPLIT * KK * NN];    // partial row sums
__device__ int    g_code;                   // 0=u8/bool, 1=int32, 2=float32

// ---------------- mask accessor ----------------
__device__ __forceinline__ unsigned mask_at(const void* m, int code, size_t idx) {
    if (code == 0)      return (unsigned)((const unsigned char*)m)[idx];
    else if (code == 1) return ((const int*)m)[idx] != 0;
    else                return __float_as_uint(((const float*)m)[idx]) != 0u;
}

// ---------------- K0: mask dtype detection ----------------
__global__ void k_detect1(const void* mask) {
    __shared__ u32 sh0, sh1;
    if (threadIdx.x == 0) { sh0 = 0u; sh1 = 0u; }
    __syncthreads();
    const u32* wp = (const u32*)mask;
    u32 o0 = 0u, o1 = 0u;
    for (int i = threadIdx.x; i < 8192; i += 256) {
        u32 v = wp[i];
        o0 |= (v & 0xFFu);
        o1 |= ((v >> 8) & 0xFFu);
    }
    atomicOr(&sh0, o0);
    atomicOr(&sh1, o1);
    __syncthreads();
    if (threadIdx.x == 0) g_code = sh1 ? 0 : (sh0 ? 1 : 2);
}

// ---------------- K0b: bit-pack mask ----------------
__global__ void __launch_bounds__(256) k_bitpack(const void* __restrict__ mask) {
    int idx = blockIdx.x * blockDim.x + threadIdx.x;
    int code = g_code;
    u32 bits = 0u;
    if (code == 0) {
        const u32* wp = (const u32*)mask + (size_t)idx * 8;
#pragma unroll
        for (int i = 0; i < 8; i++) {
            u32 v = wp[i];
            bits |= ((v & 1u) << (4 * i)) | (((v >> 8) & 1u) << (4 * i + 1)) |
                    (((v >> 16) & 1u) << (4 * i + 2)) | (((v >> 24) & 1u) << (4 * i + 3));
        }
    } else {
        size_t base = (size_t)idx * 32;
        for (int j = 0; j < 32; j++)
            bits |= mask_at(mask, code, base + j) << j;
    }
    g_mbits[idx] = bits;
}

// ---------------- K1: xe = x @ W^T + b, fused hl/hr ----------------
__global__ void __launch_bounds__(256) gemm_xe(const float* __restrict__ x,
                                               const float* __restrict__ W,
                                               const float* __restrict__ b,
                                               const float* __restrict__ aL,
                                               const float* __restrict__ aR) {
    __shared__ float sA[16][68];
    __shared__ float sB[16][68];
    int tid = threadIdx.x;
    int tx = tid & 15, ty = tid >> 4;
    int row0 = blockIdx.y * 64;
    int head = blockIdx.x;
    int col0 = head * 64;
    float acc[4][4];
#pragma unroll
    for (int i = 0; i < 4; i++)
#pragma unroll
        for (int j = 0; j < 4; j++) acc[i][j] = 0.f;

    for (int t = 0; t < FF / 16; t++) {
#pragma unroll
        for (int l = 0; l < 4; l++) {
            int idx = tid + l * 256;
            int mm = idx >> 4, kk = idx & 15;
            sA[kk][mm] = x[(size_t)(row0 + mm) * FF + t * 16 + kk];
            sB[kk][mm] = W[(size_t)(col0 + mm) * FF + t * 16 + kk];
        }
        __syncthreads();
#pragma unroll
        for (int kk = 0; kk < 16; kk++) {
            float a[4], bv[4];
#pragma unroll
            for (int i = 0; i < 4; i++) a[i] = sA[kk][ty * 4 + i];
#pragma unroll
            for (int j = 0; j < 4; j++) bv[j] = sB[kk][tx * 4 + j];
#pragma unroll
            for (int i = 0; i < 4; i++)
#pragma unroll
                for (int j = 0; j < 4; j++) acc[i][j] += a[i] * bv[j];
        }
        __syncthreads();
    }

    float hlv[4] = {0.f, 0.f, 0.f, 0.f}, hrv[4] = {0.f, 0.f, 0.f, 0.f};
#pragma unroll
    for (int j = 0; j < 4; j++) {
        int c = col0 + tx * 4 + j;
        float aLj = aL[head * FP + tx * 4 + j];
        float aRj = aR[head * FP + tx * 4 + j];
        float bj = b[c];
#pragma unroll
        for (int i = 0; i < 4; i++) {
            float v = acc[i][j] + bj;
            hlv[i] += v * aLj;
            hrv[i] += v * aRj;
            g_xe[(size_t)(row0 + ty * 4 + i) * KF + c] = v;
        }
    }
#pragma unroll
    for (int i = 0; i < 4; i++) {
#pragma unroll
        for (int off = 8; off; off >>= 1) {
            hlv[i] += __shfl_xor_sync(0xffffffffu, hlv[i], off);
            hrv[i] += __shfl_xor_sync(0xffffffffu, hrv[i], off);
        }
    }
    if (tx == 0) {
#pragma unroll
        for (int i = 0; i < 4; i++) {
            int n = row0 + ty * 4 + i;
            g_hl[head * NN + n] = hlv[i];
            g_hr[head * NN + n] = hrv[i];
        }
    }
}

// ---------------- K2: xe -> TILED fp16 xeT[k][mtile][f][32] ------------------
// One block per (mtile, head): transpose 32n x 64f, emit contiguous 4KB block.
__global__ void __launch_bounds__(128) k_xt() {
    __shared__ float tile[32][65];    // pad 65: column reads conflict-free
    int tid = threadIdx.x;
    int mt = blockIdx.x, head = blockIdx.y;

    // load 32 rows x 64 f (16 f32 per thread, float4 x4)
    int r = tid >> 2, c = (tid & 3) * 16;
    const float* src = &g_xe[(size_t)(mt * 32 + r) * KF + head * FP + c];
#pragma unroll
    for (int i = 0; i < 4; i++) {
        float4 v = *(const float4*)(src + i * 4);
        tile[r][c + i * 4 + 0] = v.x;
        tile[r][c + i * 4 + 1] = v.y;
        tile[r][c + i * 4 + 2] = v.z;
        tile[r][c + i * 4 + 3] = v.w;
    }
    __syncthreads();

    // write: thread f (0..63) emits its 32-m row as 4 uint4 (coalesced 64B/thread)
    if (tid < FP) {
        int f = tid;
        __half* dst = g_xeT + ((size_t)(head * NTA + mt) * FP + f) * BKA;
#pragma unroll
        for (int i = 0; i < 4; i++) {
            __half2 q[4];
#pragma unroll
            for (int j = 0; j < 4; j++)
                q[j] = __floats2half2_rn(tile[i * 8 + j * 2][f],
                                         tile[i * 8 + j * 2 + 1][f]);
            uint4 v = make_uint4(*(u32*)&q[0], *(u32*)&q[1],
                                 *(u32*)&q[2], *(u32*)&q[3]);
            *(uint4*)(dst + i * 8) = v;
        }
    }
}

// ---------------- K3: split-m attention (fp16 m16n8k16, double-buffered) -----
__device__ __forceinline__ float elu2(float h) {
    if (h <= 0.f) {
        h = __expf(h) - 1.0f;
        h = __expf(h) - 1.0f;
    }
    return h;
}

__global__ void __launch_bounds__(128) k_attn() {
    int kh = blockIdx.y;
    int n0 = blockIdx.x * TMA;
    int sp = blockIdx.z;
    int mbase = sp * MSPL;
    int tid = threadIdx.x;
    int lane = tid & 31, w = tid >> 5;
    int gid = lane >> 2, tig = lane & 3;
    int row0 = w * 16;

    __shared__ __align__(16) __half s_p[2][TMA][40];
    __shared__ __align__(16) __half s_xt[2][TMA][40];
    __shared__ float s_hl[TMA], s_sum[TMA];

    if (tid < TMA) s_hl[tid] = g_hl[kh * NN + n0 + tid];
    __syncthreads();

    float acc[8][4];
#pragma unroll
    for (int t = 0; t < 8; t++)
#pragma unroll
        for (int q = 0; q < 4; q++) acc[t][q] = 0.f;
    float sumreg[16];
#pragma unroll
    for (int r = 0; r < 16; r++) sumreg[r] = 0.f;

    int xr = tid >> 1;            // f row 0..63
    int xs = (tid & 1) * 16;      // half offset 0/16

#define STAGE(mb, bsel)                                                          \
    do {                                                                         \
        int m0 = mbase + (mb) * BKA;                                             \
        /* tiled xeT block: contiguous 4KB; thread reads bytes tid*32..+31 */    \
        const __half* xsrc = g_xeT +                                             \
            ((size_t)(kh * NTA + (m0 >> 5)) * FP + xr) * BKA + xs;               \
        uint4 xv0 = *(const uint4*)(xsrc);                                       \
        uint4 xv1 = *(const uint4*)(xsrc + 8);                                   \
        *(uint4*)(&s_xt[bsel][xr][xs])     = xv0;                                \
        *(uint4*)(&s_xt[bsel][xr][xs + 8]) = xv1;                                \
        float hrv = g_hr[kh * NN + m0 + lane];                                   \
        int mw = m0 >> 5;                                                        \
        _Pragma("unroll")                                                        \
        for (int r = 0; r < 16; r++) {                                           \
            int row = row0 + r;                                                  \
            u32 bt = g_mbits[(size_t)(n0 + row) * (NN / 32) + mw];               \
            float e = s_hl[row] + hrv;                                           \
            e = fmaxf(e, 0.2f * e);                                              \
            float p = ((bt >> lane) & 1u) ? __expf(e) : 0.0f;                    \
            __half ph = __float2half_rn(p);                                      \
            s_p[bsel][row][lane] = ph;                                           \
            sumreg[r] += __half2float(ph);                                       \
        }                                                                        \
    } while (0)

    STAGE(0, 0);

    for (int mb = 0; mb < TPS; mb++) {
        int cur = mb & 1;
        __syncthreads();

        if (mb + 1 < TPS) STAGE(mb + 1, cur ^ 1);

#pragma unroll
        for (int ks = 0; ks < 2; ks++) {
            int kb = ks * 16;
            u32 a0 = *(const u32*)(&s_p[cur][row0 + gid][kb + 2 * tig]);
            u32 a1 = *(const u32*)(&s_p[cur][row0 + gid + 8][kb + 2 * tig]);
            u32 a2 = *(const u32*)(&s_p[cur][row0 + gid][kb + 2 * tig + 8]);
            u32 a3 = *(const u32*)(&s_p[cur][row0 + gid + 8][kb + 2 * tig + 8]);
#pragma unroll
            for (int t = 0; t < 8; t++) {
                u32 b0 = *(const u32*)(&s_xt[cur][t * 8 + gid][kb + 2 * tig]);
                u32 b1 = *(const u32*)(&s_xt[cur][t * 8 + gid][kb + 2 * tig + 8]);
                asm("mma.sync.aligned.m16n8k16.row.col.f32.f16.f16.f32 "
                    "{%0,%1,%2,%3}, {%4,%5,%6,%7}, {%8,%9}, {%0,%1,%2,%3};"
                    : "+f"(acc[t][0]), "+f"(acc[t][1]),
                      "+f"(acc[t][2]), "+f"(acc[t][3])
                    : "r"(a0), "r"(a1), "r"(a2), "r"(a3), "r"(b0), "r"(b1));
            }
        }
    }
#undef STAGE

    // partial row sums
#pragma unroll
    for (int r = 0; r < 16; r++) {
        float s = sumreg[r];
#pragma unroll
        for (int off = 16; off; off >>= 1)
            s += __shfl_xor_sync(0xffffffffu, s, off);
        if (lane == 0) {
            s_sum[row0 + r] = s;   // unused, kept for symmetry
            g_ps[(sp * KK + kh) * NN + n0 + row0 + r] = s;
        }
    }

    // partial O (no normalize/elu)
    float* po = g_po + (size_t)sp * NN * KF;
#pragma unroll
    for (int half = 0; half < 2; half++) {
        int row = row0 + gid + half * 8;
#pragma unroll
        for (int t = 0; t < 8; t++) {
            size_t base = (size_t)(n0 + row) * KF + kh * FP + t * 8 + 2 * tig;
            *(float2*)(&po[base]) =
                make_float2(acc[t][2 * half + 0], acc[t][2 * half + 1]);
        }
    }
}

// ---------------- K4: combine splits: out = elu2((sum po)/(sum ps)) ----------
__global__ void __launch_bounds__(256) k_combine(float* __restrict__ out) {
    int n = blockIdx.x;
    int tid = threadIdx.x;
    int k = tid >> 5;                       // (tid*2)/64
    float z = g_ps[k * NN + n] + g_ps[(KK + k) * NN + n];
    float inv = 1.0f / z;
    size_t off = (size_t)n * KF + tid * 2;
    float2 o0 = *(const float2*)(&g_po[off]);
    float2 o1 = *(const float2*)(&g_po[(size_t)NN * KF + off]);
    float2 o;
    o.x = elu2((o0.x + o1.x) * inv);
    o.y = elu2((o0.y + o1.y) * inv);
    *(float2*)(&out[off]) = o;
}

// ---------------- K5: write mask back as second tuple element ----------------
__global__ void k_write_mask(const void* __restrict__ mask, float* __restrict__ out,
                             long extra) {
    int code = g_code;
    long stride = (long)gridDim.x * blockDim.x;
    for (long i = (long)blockIdx.x * blockDim.x + threadIdx.x; i < extra; i += stride) {
        float v = 0.f;
        if (i < (long)NN * NN) v = mask_at(mask, code, (size_t)i) ? 1.f : 0.f;
        out[(long)NN * KF + i] = v;
    }
}

// ---------------- launch ----------------
extern "C" void kernel_launch(void* const* d_in, const int* in_sizes, int n_in,
                              void* d_out, int out_size) {
    const float* x  = (const float*)d_in[0];
    const float* W  = (const float*)d_in[1];
    const float* b  = (const float*)d_in[2];
    const float* aL = (const float*)d_in[3];
    const float* aR = (const float*)d_in[4];
    const void*  mk = d_in[5];
    float* out = (float*)d_out;

    k_detect1<<<1, 256>>>(mk);
    k_bitpack<<<NN * (NN / 32) / 256, 256>>>(mk);

    dim3 g1(KK, NN / 64);
    gemm_xe<<<g1, 256>>>(x, W, b, aL, aR);

    dim3 g2(NTA, KK);                     // (128, 8)
    k_xt<<<g2, 128>>>();

    dim3 g3(NN / TMA, KK, SPLIT);         // (64, 8, 2) = 1024 CTAs
    k_attn<<<g3, 128>>>();

    k_combine<<<NN, 256>>>(out);

    long extra = (long)out_size - (long)NN * KF;
    if (extra > 0)
        k_write_mask<<<1024, 256>>>(mk, out, extra);
}

// round 14
// speedup vs baseline: 1.6157x; 1.0064x over previous
#include <cuda_runtime.h>
#include <cuda_fp16.h>
#include <cstddef>
#include <cstdint>

#define NN 4096
#define FF 256
#define KK 8
#define FP 64
#define KF 512   // KK*FP

#define BKA 32
#define NTA (NN / BKA)        // 128 m-tiles total
#define TMA 64                // n-rows per CTA
#define SPLIT 4
#define MSPL (NN / SPLIT)     // 1024 m per split
#define TPS (MSPL / BKA)      // 32 tiles per CTA

typedef unsigned int u32;

// ---------------- scratch (static device globals; no allocation) ----------------
__device__ float  g_xe[NN * KF];              // 8 MB xe[n][k*64+f]
__device__ __half g_xeT[KK * NTA * FP * BKA]; // 4 MB tiled: [k][mtile][f][32]
__device__ float  g_hl[KK * NN];
__device__ float  g_hr[KK * NN];
__device__ u32    g_mbits[NN * (NN / 32)];    // 2 MB bit-packed mask
__device__ float  g_po[SPLIT * NN * KF];      // 32 MB partial O
__device__ float  g_ps[SPLIT * KK * NN];      // partial row sums
__device__ int    g_code;                     // 0=u8/bool, 1=int32, 2=float32

// ---------------- mask accessor ----------------
__device__ __forceinline__ unsigned mask_at(const void* m, int code, size_t idx) {
    if (code == 0)      return (unsigned)((const unsigned char*)m)[idx];
    else if (code == 1) return ((const int*)m)[idx] != 0;
    else                return __float_as_uint(((const float*)m)[idx]) != 0u;
}

// per-block dtype detection on the first 4 KB of the mask (deterministic:
// every block scans the same region; P(wrong) ~ 2^-1024 for random masks).
// bool: byte lane 1 random -> o1 != 0. int32 0/1: o1==0, o0!=0. f32: o0==o1==0.
__device__ __forceinline__ int detect_code_block(const void* mask) {
    __shared__ u32 sh0, sh1;
    if (threadIdx.x == 0) { sh0 = 0u; sh1 = 0u; }
    __syncthreads();
    const u32* wp = (const u32*)mask;
    u32 o0 = 0u, o1 = 0u;
    for (int i = threadIdx.x; i < 1024; i += blockDim.x) {
        u32 v = wp[i];
        o0 |= (v & 0xFFu);
        o1 |= ((v >> 8) & 0xFFu);
    }
    atomicOr(&sh0, o0);
    atomicOr(&sh1, o1);
    __syncthreads();
    return sh1 ? 0 : (sh0 ? 1 : 2);
}

// ---------------- K1: bit-pack mask (detection folded in) ----------------
__global__ void __launch_bounds__(256) k_bitpack(const void* __restrict__ mask) {
    int code = detect_code_block(mask);
    if (blockIdx.x == 0 && threadIdx.x == 0) g_code = code;
    int idx = blockIdx.x * blockDim.x + threadIdx.x;   // 0 .. NN*128-1
    u32 bits = 0u;
    if (code == 0) {
        const u32* wp = (const u32*)mask + (size_t)idx * 8;
#pragma unroll
        for (int i = 0; i < 8; i++) {
            u32 v = wp[i];
            bits |= ((v & 1u) << (4 * i)) | (((v >> 8) & 1u) << (4 * i + 1)) |
                    (((v >> 16) & 1u) << (4 * i + 2)) | (((v >> 24) & 1u) << (4 * i + 3));
        }
    } else {
        size_t base = (size_t)idx * 32;
        for (int j = 0; j < 32; j++)
            bits |= mask_at(mask, code, base + j) << j;
    }
    g_mbits[idx] = bits;
}

// ---------------- K2: xe = x @ W^T + b, fused hl/hr ----------------
__global__ void __launch_bounds__(256) gemm_xe(const float* __restrict__ x,
                                               const float* __restrict__ W,
                                               const float* __restrict__ b,
                                               const float* __restrict__ aL,
                                               const float* __restrict__ aR) {
    __shared__ float sA[16][68];
    __shared__ float sB[16][68];
    int tid = threadIdx.x;
    int tx = tid & 15, ty = tid >> 4;
    int row0 = blockIdx.y * 64;
    int head = blockIdx.x;
    int col0 = head * 64;
    float acc[4][4];
#pragma unroll
    for (int i = 0; i < 4; i++)
#pragma unroll
        for (int j = 0; j < 4; j++) acc[i][j] = 0.f;

    for (int t = 0; t < FF / 16; t++) {
#pragma unroll
        for (int l = 0; l < 4; l++) {
            int idx = tid + l * 256;
            int mm = idx >> 4, kk = idx & 15;
            sA[kk][mm] = x[(size_t)(row0 + mm) * FF + t * 16 + kk];
            sB[kk][mm] = W[(size_t)(col0 + mm) * FF + t * 16 + kk];
        }
        __syncthreads();
#pragma unroll
        for (int kk = 0; kk < 16; kk++) {
            float a[4], bv[4];
#pragma unroll
            for (int i = 0; i < 4; i++) a[i] = sA[kk][ty * 4 + i];
#pragma unroll
            for (int j = 0; j < 4; j++) bv[j] = sB[kk][tx * 4 + j];
#pragma unroll
            for (int i = 0; i < 4; i++)
#pragma unroll
                for (int j = 0; j < 4; j++) acc[i][j] += a[i] * bv[j];
        }
        __syncthreads();
    }

    float hlv[4] = {0.f, 0.f, 0.f, 0.f}, hrv[4] = {0.f, 0.f, 0.f, 0.f};
#pragma unroll
    for (int j = 0; j < 4; j++) {
        int c = col0 + tx * 4 + j;
        float aLj = aL[head * FP + tx * 4 + j];
        float aRj = aR[head * FP + tx * 4 + j];
        float bj = b[c];
#pragma unroll
        for (int i = 0; i < 4; i++) {
            float v = acc[i][j] + bj;
            hlv[i] += v * aLj;
            hrv[i] += v * aRj;
            g_xe[(size_t)(row0 + ty * 4 + i) * KF + c] = v;
        }
    }
#pragma unroll
    for (int i = 0; i < 4; i++) {
#pragma unroll
        for (int off = 8; off; off >>= 1) {
            hlv[i] += __shfl_xor_sync(0xffffffffu, hlv[i], off);
            hrv[i] += __shfl_xor_sync(0xffffffffu, hrv[i], off);
        }
    }
    if (tx == 0) {
#pragma unroll
        for (int i = 0; i < 4; i++) {
            int n = row0 + ty * 4 + i;
            g_hl[head * NN + n] = hlv[i];
            g_hr[head * NN + n] = hrv[i];
        }
    }
}

// ---------------- K3: xe -> TILED fp16 xeT[k][mtile][f][32] ------------------
__global__ void __launch_bounds__(128) k_xt() {
    __shared__ float tile[32][65];
    int tid = threadIdx.x;
    int mt = blockIdx.x, head = blockIdx.y;

    int r = tid >> 2, c = (tid & 3) * 16;
    const float* src = &g_xe[(size_t)(mt * 32 + r) * KF + head * FP + c];
#pragma unroll
    for (int i = 0; i < 4; i++) {
        float4 v = *(const float4*)(src + i * 4);
        tile[r][c + i * 4 + 0] = v.x;
        tile[r][c + i * 4 + 1] = v.y;
        tile[r][c + i * 4 + 2] = v.z;
        tile[r][c + i * 4 + 3] = v.w;
    }
    __syncthreads();

    if (tid < FP) {
        int f = tid;
        __half* dst = g_xeT + ((size_t)(head * NTA + mt) * FP + f) * BKA;
#pragma unroll
        for (int i = 0; i < 4; i++) {
            __half2 q[4];
#pragma unroll
            for (int j = 0; j < 4; j++)
                q[j] = __floats2half2_rn(tile[i * 8 + j * 2][f],
                                         tile[i * 8 + j * 2 + 1][f]);
            uint4 v = make_uint4(*(u32*)&q[0], *(u32*)&q[1],
                                 *(u32*)&q[2], *(u32*)&q[3]);
            *(uint4*)(dst + i * 8) = v;
        }
    }
}

// ---------------- K4: split-m attention (fp16 m16n8k16, double-buffered) -----
__device__ __forceinline__ float elu2(float h) {
    if (h <= 0.f) {
        h = __expf(h) - 1.0f;
        h = __expf(h) - 1.0f;
    }
    return h;
}

__global__ void __launch_bounds__(128) k_attn() {
    int kh = blockIdx.y;
    int n0 = blockIdx.x * TMA;
    int sp = blockIdx.z;
    int mbase = sp * MSPL;
    int tid = threadIdx.x;
    int lane = tid & 31, w = tid >> 5;
    int gid = lane >> 2, tig = lane & 3;
    int row0 = w * 16;

    __shared__ __align__(16) __half s_p[2][TMA][40];
    __shared__ __align__(16) __half s_xt[2][TMA][40];
    __shared__ float s_hl[TMA];

    if (tid < TMA) s_hl[tid] = g_hl[kh * NN + n0 + tid];
    __syncthreads();

    float acc[8][4];
#pragma unroll
    for (int t = 0; t < 8; t++)
#pragma unroll
        for (int q = 0; q < 4; q++) acc[t][q] = 0.f;
    float sumreg[16];
#pragma unroll
    for (int r = 0; r < 16; r++) sumreg[r] = 0.f;

    int xr = tid >> 1;            // f row 0..63
    int xs = (tid & 1) * 16;      // half offset 0/16

#define STAGE(mb, bsel)                                                          \
    do {                                                                         \
        int m0 = mbase + (mb) * BKA;                                             \
        const __half* xsrc = g_xeT +                                             \
            ((size_t)(kh * NTA + (m0 >> 5)) * FP + xr) * BKA + xs;               \
        uint4 xv0 = *(const uint4*)(xsrc);                                       \
        uint4 xv1 = *(const uint4*)(xsrc + 8);                                   \
        *(uint4*)(&s_xt[bsel][xr][xs])     = xv0;                                \
        *(uint4*)(&s_xt[bsel][xr][xs + 8]) = xv1;                                \
        float hrv = g_hr[kh * NN + m0 + lane];                                   \
        int mw = m0 >> 5;                                                        \
        _Pragma("unroll")                                                        \
        for (int r = 0; r < 16; r++) {                                           \
            int row = row0 + r;                                                  \
            u32 bt = g_mbits[(size_t)(n0 + row) * (NN / 32) + mw];               \
            float e = s_hl[row] + hrv;                                           \
            e = fmaxf(e, 0.2f * e);                                              \
            float p = ((bt >> lane) & 1u) ? __expf(e) : 0.0f;                    \
            __half ph = __float2half_rn(p);                                      \
            s_p[bsel][row][lane] = ph;                                           \
            sumreg[r] += __half2float(ph);                                       \
        }                                                                        \
    } while (0)

    STAGE(0, 0);

    for (int mb = 0; mb < TPS; mb++) {
        int cur = mb & 1;
        __syncthreads();

        if (mb + 1 < TPS) STAGE(mb + 1, cur ^ 1);

#pragma unroll
        for (int ks = 0; ks < 2; ks++) {
            int kb = ks * 16;
            u32 a0 = *(const u32*)(&s_p[cur][row0 + gid][kb + 2 * tig]);
            u32 a1 = *(const u32*)(&s_p[cur][row0 + gid + 8][kb + 2 * tig]);
            u32 a2 = *(const u32*)(&s_p[cur][row0 + gid][kb + 2 * tig + 8]);
            u32 a3 = *(const u32*)(&s_p[cur][row0 + gid + 8][kb + 2 * tig + 8]);
#pragma unroll
            for (int t = 0; t < 8; t++) {
                u32 b0 = *(const u32*)(&s_xt[cur][t * 8 + gid][kb + 2 * tig]);
                u32 b1 = *(const u32*)(&s_xt[cur][t * 8 + gid][kb + 2 * tig + 8]);
                asm("mma.sync.aligned.m16n8k16.row.col.f32.f16.f16.f32 "
                    "{%0,%1,%2,%3}, {%4,%5,%6,%7}, {%8,%9}, {%0,%1,%2,%3};"
                    : "+f"(acc[t][0]), "+f"(acc[t][1]),
                      "+f"(acc[t][2]), "+f"(acc[t][3])
                    : "r"(a0), "r"(a1), "r"(a2), "r"(a3), "r"(b0), "r"(b1));
            }
        }
    }
#undef STAGE

    // partial row sums -> global
#pragma unroll
    for (int r = 0; r < 16; r++) {
        float s = sumreg[r];
#pragma unroll
        for (int off = 16; off; off >>= 1)
            s += __shfl_xor_sync(0xffffffffu, s, off);
        if (lane == 0)
            g_ps[(sp * KK + kh) * NN + n0 + row0 + r] = s;
    }

    // partial O (no normalize/elu)
    float* po = g_po + (size_t)sp * NN * KF;
#pragma unroll
    for (int half = 0; half < 2; half++) {
        int row = row0 + gid + half * 8;
#pragma unroll
        for (int t = 0; t < 8; t++) {
            size_t base = (size_t)(n0 + row) * KF + kh * FP + t * 8 + 2 * tig;
            *(float2*)(&po[base]) =
                make_float2(acc[t][2 * half + 0], acc[t][2 * half + 1]);
        }
    }
}

// ---------------- K5: combine splits: out = elu2((sum po)/(sum ps)) ----------
__global__ void __launch_bounds__(256) k_combine(float* __restrict__ out) {
    int n = blockIdx.x;
    int tid = threadIdx.x;
    int k = tid >> 5;
    float z = 0.f;
#pragma unroll
    for (int sp = 0; sp < SPLIT; sp++)
        z += g_ps[(sp * KK + k) * NN + n];
    float inv = 1.0f / z;
    size_t off = (size_t)n * KF + tid * 2;
    float ox = 0.f, oy = 0.f;
#pragma unroll
    for (int sp = 0; sp < SPLIT; sp++) {
        float2 o = *(const float2*)(&g_po[(size_t)sp * NN * KF + off]);
        ox += o.x;
        oy += o.y;
    }
    *(float2*)(&out[off]) = make_float2(elu2(ox * inv), elu2(oy * inv));
}

// ---------------- K6: write mask back as second tuple element ----------------
__global__ void __launch_bounds__(256) k_write_mask(const void* __restrict__ mask,
                                                    float* __restrict__ out,
                                                    long extra) {
    int code = detect_code_block(mask);
    long stride = (long)gridDim.x * blockDim.x;
    for (long i = (long)blockIdx.x * blockDim.x + threadIdx.x; i < extra; i += stride) {
        float v = 0.f;
        if (i < (long)NN * NN) v = mask_at(mask, code, (size_t)i) ? 1.f : 0.f;
        out[(long)NN * KF + i] = v;
    }
}

// ---------------- launch ----------------
extern "C" void kernel_launch(void* const* d_in, const int* in_sizes, int n_in,
                              void* d_out, int out_size) {
    const float* x  = (const float*)d_in[0];
    const float* W  = (const float*)d_in[1];
    const float* b  = (const float*)d_in[2];
    const float* aL = (const float*)d_in[3];
    const float* aR = (const float*)d_in[4];
    const void*  mk = d_in[5];
    float* out = (float*)d_out;

    k_bitpack<<<NN * (NN / 32) / 256, 256>>>(mk);        // 1

    dim3 g1(KK, NN / 64);
    gemm_xe<<<g1, 256>>>(x, W, b, aL, aR);               // 2

    dim3 g2(NTA, KK);
    k_xt<<<g2, 128>>>();                                 // 3

    dim3 g3(NN / TMA, KK, SPLIT);                        // (64, 8, 4) = 2048 CTAs
    k_attn<<<g3, 128>>>();                               // 4  <- ncu capture slot

    k_combine<<<NN, 256>>>(out);                         // 5

    long extra = (long)out_size - (long)NN * KF;
    if (extra > 0)
        k_write_mask<<<1024, 256>>>(mk, out, extra);     // 6
}